// round 15
// baseline (speedup 1.0000x reference)
#include <cuda_runtime.h>
#include <cstdint>

#define N_NODES 8192
#define F_DIM   2048
#define E_EDGES 262144
#define H1      32
#define H2      16
#define ALPHA   0.9f

typedef unsigned long long ull;

// ---------------- scratch (device globals; no allocs allowed) ----------------
__device__ float g_deg  [N_NODES];
__device__ float g_WT   [H1 * F_DIM];     // W0 transposed: [n][k]
__device__ float g_xw   [N_NODES * H1];
__device__ float g_agg1 [N_NODES * H1];
__device__ float g_h    [N_NODES * H1];
__device__ float g_hw   [N_NODES * H2];
__device__ float g_agg2 [N_NODES * H2];
__device__ float g_zauto[N_NODES * H1];
__device__ float g_z    [N_NODES * H2];

// ---------------- f32x2 / misc helpers ----------------
__device__ __forceinline__ ull dup2(float x) {
    ull r; asm("mov.b64 %0, {%1, %1};" : "=l"(r) : "f"(x)); return r;
}
__device__ __forceinline__ void ffma2(ull& d, ull a, ull b) {
    asm("fma.rn.f32x2 %0, %1, %2, %0;" : "+l"(d) : "l"(a), "l"(b));
}
__device__ __forceinline__ float2 unpk(ull v) {
    float2 r; asm("mov.b64 {%0, %1}, %2;" : "=f"(r.x), "=f"(r.y) : "l"(v)); return r;
}
__device__ __forceinline__ void red4(float* p, float a, float b, float c, float d) {
    asm volatile("red.global.add.v4.f32 [%0], {%1,%2,%3,%4};"
                 :: "l"(p), "f"(a), "f"(b), "f"(c), "f"(d) : "memory");
}
// streaming 16B store (evict-first; output is never re-read)
__device__ __forceinline__ void stcs4(float* p, float4 v) {
    asm volatile("st.global.cs.v4.f32 [%0], {%1,%2,%3,%4};"
                 :: "l"(p), "f"(v.x), "f"(v.y), "f"(v.z), "f"(v.w) : "memory");
}
// inline degree norm: deg^{-1/2} with clamp
__device__ __forceinline__ float dnorm(int node) {
    return rsqrtf(fmaxf(g_deg[node], 1.0f));
}
// sigmoid via single-MUFU hardware tanh: sigm(x) = 0.5*tanh(x/2) + 0.5
__device__ __forceinline__ float sigm(float x) {
    float t;
    asm("tanh.approx.f32 %0, %1;" : "=f"(t) : "f"(0.5f * x));
    return fmaf(0.5f, t, 0.5f);
}

// ---------------- init: zero scratch + build WT (fused) ----------------
__global__ void init_kernel(const float* __restrict__ W0) {
    int i = blockIdx.x * blockDim.x + threadIdx.x;
    if (i < N_NODES) g_deg[i] = 0.f;
    if (i < N_NODES * H1) { g_xw[i] = 0.f; g_agg1[i] = 0.f; g_zauto[i] = 0.f; }
    if (i < N_NODES * H2) g_agg2[i] = 0.f;
    if (i < H1 * F_DIM) {
        int k = i >> 5, n = i & 31;
        g_WT[n * F_DIM + k] = W0[i];
    }
}

// ---------------- degree ----------------
__global__ void deg_kernel(const int* __restrict__ dst) {
    int i = blockIdx.x * blockDim.x + threadIdx.x;
    if (i < E_EDGES) atomicAdd(&g_deg[dst[i]], 1.0f);
}

// ---------------- GEMM1: xw = feat @ W0 (R13 known-good; converged) ----------
// BM=128, N=32, K-slice=128 (4 tiles of BK=32), SPLITK=16 -> grid (64,16).
// f32x2 pairs over K; 3 blocks/SM via launch_bounds; no register prefetch.
__global__ __launch_bounds__(256, 3) void gemm1_kernel(const float* __restrict__ feat) {
    __shared__ float fs[128][36];    // [row][k] plain; stride 36 -> 16B-aligned rows
    __shared__ float wsT[32][132];   // [col][k] whole 128-k slice; stride 132

    const int tid = threadIdx.x;
    const int rowBase = blockIdx.x * 128;
    const int kBase   = blockIdx.y * 128;
    const int tx = tid & 7, ty = tid >> 3;
    const int r0 = ty * 4;

    const float* fb = feat + (size_t)rowBase * F_DIM + kBase;

    // ---- load whole B slice (32 cols x 128 k) once ----
    {
        int c = tid >> 3, j0 = tid & 7;
        const float* wrow = &g_WT[(size_t)c * F_DIM + kBase];
        #pragma unroll
        for (int i = 0; i < 4; i++) {
            int kk = (j0 + 8 * i) * 4;
            *(float4*)&wsT[c][kk] = *(const float4*)&wrow[kk];
        }
    }

    int row_[4], kq_[4];
    #pragma unroll
    for (int i = 0; i < 4; i++) { int s = i * 256 + tid; row_[i] = s >> 3; kq_[i] = s & 7; }

    ull acc[4][4] = {};   // [row i][col j], pair = (even-k sum, odd-k sum)

    #pragma unroll
    for (int t = 0; t < 4; t++) {
        #pragma unroll
        for (int i = 0; i < 4; i++)
            *(float4*)&fs[row_[i]][kq_[i] * 4] =
                *(const float4*)&fb[(size_t)row_[i] * F_DIM + t * 32 + kq_[i] * 4];
        __syncthreads();

        const int kw = t * 32;
        #pragma unroll
        for (int k = 0; k < 32; k += 4) {
            ulonglong2 A[4], B[4];
            #pragma unroll
            for (int i = 0; i < 4; i++)
                A[i] = *(ulonglong2*)&fs[r0 + i][k];
            #pragma unroll
            for (int j = 0; j < 4; j++)
                B[j] = *(ulonglong2*)&wsT[tx + 8 * j][kw + k];
            #pragma unroll
            for (int i = 0; i < 4; i++)
                #pragma unroll
                for (int j = 0; j < 4; j++) {
                    ffma2(acc[i][j], A[i].x, B[j].x);
                    ffma2(acc[i][j], A[i].y, B[j].y);
                }
        }
        __syncthreads();
    }

    // ---- epilogue: stage partial tile in fs, then contiguous red.v4 ----
    #pragma unroll
    for (int i = 0; i < 4; i++)
        #pragma unroll
        for (int j = 0; j < 4; j++) {
            float2 p = unpk(acc[i][j]);
            fs[r0 + i][tx + 8 * j] = p.x + p.y;
        }
    __syncthreads();

    {
        int row = tid >> 1, cs = (tid & 1) * 16;
        float* gp = &g_xw[(size_t)(rowBase + row) * H1 + cs];
        #pragma unroll
        for (int q = 0; q < 4; q++) {
            float4 v = *(float4*)&fs[row][cs + q * 4];
            red4(gp + q * 4, v.x, v.y, v.z, v.w);
        }
    }
}

// ---------------- edge pass 1: agg1[dst] += norm[src] * xw[src] --------------
// 4 lanes/edge, 2 float4 per lane (MLP=2 against L2 gather latency)
__global__ void edge_h_kernel(const int* __restrict__ src, const int* __restrict__ dst) {
    int t = blockIdx.x * blockDim.x + threadIdx.x;
    int e = t >> 2, q = t & 3;
    if (e >= E_EDGES) return;
    int s = __ldg(&src[e]);
    int d = __ldg(&dst[e]);
    float ns = dnorm(s);
    const float* xp = &g_xw[s * H1 + q * 8];
    float4 v0 = *(const float4*)xp;
    float4 v1 = *(const float4*)(xp + 4);
    float* ap = &g_agg1[d * H1 + q * 8];
    red4(ap,     v0.x * ns, v0.y * ns, v0.z * ns, v0.w * ns);
    red4(ap + 4, v1.x * ns, v1.y * ns, v1.z * ns, v1.w * ns);
}

// ---------------- fused: h = relu(norm*agg1); hw = norm*(h @ Wm) -------------
__global__ __launch_bounds__(256) void relu_hw_kernel(const float* __restrict__ Wm) {
    __shared__ float sh[8][33];
    int tid = threadIdx.x;
    int local = tid >> 5, lane = tid & 31;
    int node = blockIdx.x * 8 + local;
    float h = fmaxf(dnorm(node) * g_agg1[node * H1 + lane], 0.0f);
    g_h[node * H1 + lane] = h;
    sh[local][lane] = h;
    __syncthreads();
    if (tid < 128) {
        int ln = tid >> 4, j = tid & 15;
        int nd = blockIdx.x * 8 + ln;
        float sum = 0.f;
        #pragma unroll
        for (int c = 0; c < H1; c++)
            sum += sh[ln][c] * __ldg(&Wm[c * H2 + j]);
        g_hw[nd * H2 + j] = dnorm(nd) * sum;
    }
}

// ---------------- edge pass 2: gate + z_auto + agg2 (fused, 4 lanes/edge) ----
__global__ void edge2_kernel(const int* __restrict__ src, const int* __restrict__ dst,
                             const float* __restrict__ gate_w,
                             const float* __restrict__ gate_b) {
    int t = blockIdx.x * blockDim.x + threadIdx.x;
    int e = t >> 2, q = t & 3;
    if (e >= E_EDGES) return;
    int s = __ldg(&src[e]);
    int d = __ldg(&dst[e]);
    const float* hsp = &g_h[s * H1 + q * 8];
    const float* hdp = &g_h[d * H1 + q * 8];
    float4 hs0 = *(const float4*)hsp,       hs1 = *(const float4*)(hsp + 4);
    float4 hd0 = *(const float4*)hdp,       hd1 = *(const float4*)(hdp + 4);
    float4 w00 = __ldg((const float4*)&gate_w[q * 8]);
    float4 w01 = __ldg((const float4*)&gate_w[q * 8 + 4]);
    float4 w10 = __ldg((const float4*)&gate_w[H1 + q * 8]);
    float4 w11 = __ldg((const float4*)&gate_w[H1 + q * 8 + 4]);
    float gp = hd0.x * w00.x + hd0.y * w00.y + hd0.z * w00.z + hd0.w * w00.w
             + hd1.x * w01.x + hd1.y * w01.y + hd1.z * w01.z + hd1.w * w01.w
             + hs0.x * w10.x + hs0.y * w10.y + hs0.z * w10.z + hs0.w * w10.w
             + hs1.x * w11.x + hs1.y * w11.y + hs1.z * w11.z + hs1.w * w11.w;
    gp += __shfl_xor_sync(0xffffffffu, gp, 1);
    gp += __shfl_xor_sync(0xffffffffu, gp, 2);
    float g  = tanhf(gp + __ldg(&gate_b[0]));
    float ew = g * dnorm(d) * dnorm(s) * ALPHA;
    float* zp = &g_zauto[d * H1 + q * 8];
    red4(zp,     hs0.x * ew, hs0.y * ew, hs0.z * ew, hs0.w * ew);
    red4(zp + 4, hs1.x * ew, hs1.y * ew, hs1.z * ew, hs1.w * ew);
    {   // agg2: 4 lanes cover H2=16 with one float4 each
        float4 hw = *(const float4*)&g_hw[s * H2 + q * 4];
        red4(&g_agg2[d * H2 + q * 4], hw.x, hw.y, hw.z, hw.w);
    }
}

// ---------------- z = noise * exp((z_auto + a*h) @ t2w) + norm*agg2 ----------
__global__ void nodez_kernel(const float* __restrict__ t2w,
                             const float* __restrict__ noise) {
    int t = blockIdx.x * blockDim.x + threadIdx.x;
    if (t >= N_NODES * H2) return;
    int node = t >> 4, j = t & 15;
    float mean = dnorm(node) * g_agg2[t];
    float sum = 0.f;
    #pragma unroll
    for (int c = 0; c < H1; c++)
        sum += (g_zauto[node * H1 + c] + ALPHA * g_h[node * H1 + c]) * __ldg(&t2w[c * H2 + j]);
    g_z[t] = noise[t] * expf(sum) + mean;
}

// ---------------- out = sigmoid(z @ z^T), 128x128 tiles, 8x8/thread, f32x2 ---
__global__ __launch_bounds__(256) void zzt_kernel(float* __restrict__ out) {
    __shared__ float zr[H2][132];   // [k][row]
    __shared__ float zc[H2][132];   // [k][col]

    const int tid = threadIdx.x;
    const int rb = blockIdx.y * 128, cb = blockIdx.x * 128;

    #pragma unroll
    for (int i = 0; i < 2; i++) {
        int sIdx = tid + i * 256;
        int row = sIdx >> 2, kq = sIdx & 3;
        float4 v = *(const float4*)&g_z[(size_t)(rb + row) * H2 + kq * 4];
        zr[kq * 4 + 0][row] = v.x; zr[kq * 4 + 1][row] = v.y;
        zr[kq * 4 + 2][row] = v.z; zr[kq * 4 + 3][row] = v.w;
        float4 w = *(const float4*)&g_z[(size_t)(cb + row) * H2 + kq * 4];
        zc[kq * 4 + 0][row] = w.x; zc[kq * 4 + 1][row] = w.y;
        zc[kq * 4 + 2][row] = w.z; zc[kq * 4 + 3][row] = w.w;
    }
    __syncthreads();

    const int tc = tid & 15, tr = tid >> 4;
    const int r4 = tr * 4, c4 = tc * 4;

    ull acc[8][4] = {};
    #pragma unroll
    for (int k = 0; k < H2; k++) {
        float4 a0 = *(const float4*)&zr[k][r4];
        float4 a1 = *(const float4*)&zr[k][r4 + 64];
        ulonglong2 b01 = *(ulonglong2*)&zc[k][c4];
        ulonglong2 b23 = *(ulonglong2*)&zc[k][c4 + 64];
        ull a[8] = { dup2(a0.x), dup2(a0.y), dup2(a0.z), dup2(a0.w),
                     dup2(a1.x), dup2(a1.y), dup2(a1.z), dup2(a1.w) };
        ull b[4] = { b01.x, b01.y, b23.x, b23.y };
        #pragma unroll
        for (int i = 0; i < 8; i++) {
            ffma2(acc[i][0], a[i], b[0]);
            ffma2(acc[i][1], a[i], b[1]);
            ffma2(acc[i][2], a[i], b[2]);
            ffma2(acc[i][3], a[i], b[3]);
        }
    }

    #pragma unroll
    for (int i = 0; i < 8; i++) {
        int row = rb + r4 + (i < 4 ? i : 60 + i);
        float2 p0 = unpk(acc[i][0]), p1 = unpk(acc[i][1]);
        float2 p2 = unpk(acc[i][2]), p3 = unpk(acc[i][3]);
        float4 o0, o1;
        o0.x = sigm(p0.x); o0.y = sigm(p0.y); o0.z = sigm(p1.x); o0.w = sigm(p1.y);
        o1.x = sigm(p2.x); o1.y = sigm(p2.y); o1.z = sigm(p3.x); o1.w = sigm(p3.y);
        stcs4(&out[(size_t)row * N_NODES + cb + c4],      o0);
        stcs4(&out[(size_t)row * N_NODES + cb + c4 + 64], o1);
    }
}

// ---------------- launcher ----------------
extern "C" void kernel_launch(void* const* d_in, const int* in_sizes, int n_in,
                              void* d_out, int out_size) {
    const float* feat   = (const float*)d_in[0];
    const float* W0     = (const float*)d_in[1];
    const float* Wm     = (const float*)d_in[2];
    const float* gate_w = (const float*)d_in[3];
    const float* gate_b = (const float*)d_in[4];
    const float* t2w    = (const float*)d_in[5];
    const float* noise  = (const float*)d_in[6];
    const int*   src    = (const int*)d_in[7];
    const int*   dst    = (const int*)d_in[8];
    float* out = (float*)d_out;

    init_kernel<<<(N_NODES * H1) / 256, 256>>>(W0);
    deg_kernel<<<E_EDGES / 256, 256>>>(dst);
    gemm1_kernel<<<dim3(N_NODES / 128, 16), 256>>>(feat);
    edge_h_kernel<<<(E_EDGES * 4) / 256, 256>>>(src, dst);
    relu_hw_kernel<<<N_NODES / 8, 256>>>(Wm);
    edge2_kernel<<<(E_EDGES * 4) / 256, 256>>>(src, dst, gate_w, gate_b);
    nodez_kernel<<<(N_NODES * H2) / 256, 256>>>(t2w, noise);
    zzt_kernel<<<dim3(64, 64), 256>>>(out);
}

// round 16
// speedup vs baseline: 1.2141x; 1.2141x over previous
#include <cuda_runtime.h>
#include <cstdint>

#define N_NODES 8192
#define F_DIM   2048
#define E_EDGES 262144
#define H1      32
#define H2      16
#define ALPHA   0.9f

typedef unsigned long long ull;

// ---------------- scratch (device globals; no allocs allowed) ----------------
__device__ float g_deg  [N_NODES];
__device__ float g_WT   [H1 * F_DIM];     // W0 transposed: [n][k]
__device__ float g_xw   [N_NODES * H1];
__device__ float g_agg1 [N_NODES * H1];
__device__ float g_h    [N_NODES * H1];
__device__ float g_hw   [N_NODES * H2];
__device__ float g_agg2 [N_NODES * H2];
__device__ float g_zauto[N_NODES * H1];
__device__ float g_z    [N_NODES * H2];

// ---------------- f32x2 / misc helpers ----------------
__device__ __forceinline__ ull dup2(float x) {
    ull r; asm("mov.b64 %0, {%1, %1};" : "=l"(r) : "f"(x)); return r;
}
__device__ __forceinline__ void ffma2(ull& d, ull a, ull b) {
    asm("fma.rn.f32x2 %0, %1, %2, %0;" : "+l"(d) : "l"(a), "l"(b));
}
__device__ __forceinline__ float2 unpk(ull v) {
    float2 r; asm("mov.b64 {%0, %1}, %2;" : "=f"(r.x), "=f"(r.y) : "l"(v)); return r;
}
__device__ __forceinline__ void red4(float* p, float a, float b, float c, float d) {
    asm volatile("red.global.add.v4.f32 [%0], {%1,%2,%3,%4};"
                 :: "l"(p), "f"(a), "f"(b), "f"(c), "f"(d) : "memory");
}
__device__ __forceinline__ void red1(float* p, float a) {
    asm volatile("red.global.add.f32 [%0], %1;" :: "l"(p), "f"(a) : "memory");
}
// streaming 16B store (evict-first; output is never re-read)
__device__ __forceinline__ void stcs4(float* p, float4 v) {
    asm volatile("st.global.cs.v4.f32 [%0], {%1,%2,%3,%4};"
                 :: "l"(p), "f"(v.x), "f"(v.y), "f"(v.z), "f"(v.w) : "memory");
}
// inline degree norm: deg^{-1/2} with clamp
__device__ __forceinline__ float dnorm(int node) {
    return rsqrtf(fmaxf(g_deg[node], 1.0f));
}
// sigmoid via single-MUFU hardware tanh: sigm(x) = 0.5*tanh(x/2) + 0.5
__device__ __forceinline__ float sigm(float x) {
    float t;
    asm("tanh.approx.f32 %0, %1;" : "=f"(t) : "f"(0.5f * x));
    return fmaf(0.5f, t, 0.5f);
}

// ---------------- init: zero scratch + build WT (fused) ----------------
__global__ void init_kernel(const float* __restrict__ W0) {
    int i = blockIdx.x * blockDim.x + threadIdx.x;
    if (i < N_NODES) g_deg[i] = 0.f;
    if (i < N_NODES * H1) { g_xw[i] = 0.f; g_agg1[i] = 0.f; g_zauto[i] = 0.f; }
    if (i < N_NODES * H2) g_agg2[i] = 0.f;
    if (i < H1 * F_DIM) {
        int k = i >> 5, n = i & 31;
        g_WT[n * F_DIM + k] = W0[i];
    }
}

// ---------------- GEMM1: xw = feat @ W0 (R13 converged) + fused deg ---------
// BM=128, N=32, K-slice=128 (4 tiles of BK=32), SPLITK=16 -> grid (64,16).
// grid*block = 262144 threads = E_EDGES exactly: each thread also issues one
// degree RED at entry; the atomic traffic hides in gemm1's idle issue slots,
// and edge_h (launched after) sees a complete g_deg. Kills a ~5us serialized
// launch.
__global__ __launch_bounds__(256, 3) void gemm1_kernel(const float* __restrict__ feat,
                                                       const int* __restrict__ dst) {
    __shared__ float fs[128][36];    // [row][k] plain; stride 36 -> 16B-aligned rows
    __shared__ float wsT[32][132];   // [col][k] whole 128-k slice; stride 132

    const int tid = threadIdx.x;
    const int rowBase = blockIdx.x * 128;
    const int kBase   = blockIdx.y * 128;
    const int tx = tid & 7, ty = tid >> 3;
    const int r0 = ty * 4;

    // ---- fused degree count: one edge per thread ----
    {
        int e = (blockIdx.y * 64 + blockIdx.x) * 256 + tid;
        red1(&g_deg[__ldg(&dst[e])], 1.0f);
    }

    const float* fb = feat + (size_t)rowBase * F_DIM + kBase;

    // ---- load whole B slice (32 cols x 128 k) once ----
    {
        int c = tid >> 3, j0 = tid & 7;
        const float* wrow = &g_WT[(size_t)c * F_DIM + kBase];
        #pragma unroll
        for (int i = 0; i < 4; i++) {
            int kk = (j0 + 8 * i) * 4;
            *(float4*)&wsT[c][kk] = *(const float4*)&wrow[kk];
        }
    }

    int row_[4], kq_[4];
    #pragma unroll
    for (int i = 0; i < 4; i++) { int s = i * 256 + tid; row_[i] = s >> 3; kq_[i] = s & 7; }

    ull acc[4][4] = {};   // [row i][col j], pair = (even-k sum, odd-k sum)

    #pragma unroll
    for (int t = 0; t < 4; t++) {
        #pragma unroll
        for (int i = 0; i < 4; i++)
            *(float4*)&fs[row_[i]][kq_[i] * 4] =
                *(const float4*)&fb[(size_t)row_[i] * F_DIM + t * 32 + kq_[i] * 4];
        __syncthreads();

        const int kw = t * 32;
        #pragma unroll
        for (int k = 0; k < 32; k += 4) {
            ulonglong2 A[4], B[4];
            #pragma unroll
            for (int i = 0; i < 4; i++)
                A[i] = *(ulonglong2*)&fs[r0 + i][k];
            #pragma unroll
            for (int j = 0; j < 4; j++)
                B[j] = *(ulonglong2*)&wsT[tx + 8 * j][kw + k];
            #pragma unroll
            for (int i = 0; i < 4; i++)
                #pragma unroll
                for (int j = 0; j < 4; j++) {
                    ffma2(acc[i][j], A[i].x, B[j].x);
                    ffma2(acc[i][j], A[i].y, B[j].y);
                }
        }
        __syncthreads();
    }

    // ---- epilogue: stage partial tile in fs, then contiguous red.v4 ----
    #pragma unroll
    for (int i = 0; i < 4; i++)
        #pragma unroll
        for (int j = 0; j < 4; j++) {
            float2 p = unpk(acc[i][j]);
            fs[r0 + i][tx + 8 * j] = p.x + p.y;
        }
    __syncthreads();

    {
        int row = tid >> 1, cs = (tid & 1) * 16;
        float* gp = &g_xw[(size_t)(rowBase + row) * H1 + cs];
        #pragma unroll
        for (int q = 0; q < 4; q++) {
            float4 v = *(float4*)&fs[row][cs + q * 4];
            red4(gp + q * 4, v.x, v.y, v.z, v.w);
        }
    }
}

// ---------------- edge pass 1: agg1[dst] += norm[src] * xw[src] --------------
// (R13 form: 8 lanes/edge — warp-parallelism-bound, keep max warps)
__global__ void edge_h_kernel(const int* __restrict__ src, const int* __restrict__ dst) {
    int t = blockIdx.x * blockDim.x + threadIdx.x;
    int e = t >> 3, q = t & 7;
    if (e >= E_EDGES) return;
    int s = __ldg(&src[e]);
    int d = __ldg(&dst[e]);
    float ns = dnorm(s);
    float4 v = *(const float4*)&g_xw[s * H1 + q * 4];
    red4(&g_agg1[d * H1 + q * 4], v.x * ns, v.y * ns, v.z * ns, v.w * ns);
}

// ---------------- fused: h = relu(norm*agg1); hw = norm*(h @ Wm) -------------
__global__ __launch_bounds__(256) void relu_hw_kernel(const float* __restrict__ Wm) {
    __shared__ float sh[8][33];
    int tid = threadIdx.x;
    int local = tid >> 5, lane = tid & 31;
    int node = blockIdx.x * 8 + local;
    float h = fmaxf(dnorm(node) * g_agg1[node * H1 + lane], 0.0f);
    g_h[node * H1 + lane] = h;
    sh[local][lane] = h;
    __syncthreads();
    if (tid < 128) {
        int ln = tid >> 4, j = tid & 15;
        int nd = blockIdx.x * 8 + ln;
        float sum = 0.f;
        #pragma unroll
        for (int c = 0; c < H1; c++)
            sum += sh[ln][c] * __ldg(&Wm[c * H2 + j]);
        g_hw[nd * H2 + j] = dnorm(nd) * sum;
    }
}

// ---------------- edge pass 2: gate + z_auto + agg2 (R13 form, 8 lanes) ------
__global__ void edge2_kernel(const int* __restrict__ src, const int* __restrict__ dst,
                             const float* __restrict__ gate_w,
                             const float* __restrict__ gate_b) {
    int t = blockIdx.x * blockDim.x + threadIdx.x;
    int e = t >> 3, q = t & 7;
    if (e >= E_EDGES) return;
    int s = __ldg(&src[e]);
    int d = __ldg(&dst[e]);
    float4 hs = *(const float4*)&g_h[s * H1 + q * 4];
    float4 hd = *(const float4*)&g_h[d * H1 + q * 4];
    float4 w0 = __ldg((const float4*)&gate_w[q * 4]);
    float4 w1 = __ldg((const float4*)&gate_w[H1 + q * 4]);
    float gp = hd.x * w0.x + hd.y * w0.y + hd.z * w0.z + hd.w * w0.w
             + hs.x * w1.x + hs.y * w1.y + hs.z * w1.z + hs.w * w1.w;
    gp += __shfl_xor_sync(0xffffffffu, gp, 1);
    gp += __shfl_xor_sync(0xffffffffu, gp, 2);
    gp += __shfl_xor_sync(0xffffffffu, gp, 4);
    float g  = tanhf(gp + __ldg(&gate_b[0]));
    float ew = g * dnorm(d) * dnorm(s) * ALPHA;
    red4(&g_zauto[d * H1 + q * 4], hs.x * ew, hs.y * ew, hs.z * ew, hs.w * ew);
    if (q < 4) {
        float4 hw = *(const float4*)&g_hw[s * H2 + q * 4];
        red4(&g_agg2[d * H2 + q * 4], hw.x, hw.y, hw.z, hw.w);
    }
}

// ---------------- z = noise * exp((z_auto + a*h) @ t2w) + norm*agg2 ----------
__global__ void nodez_kernel(const float* __restrict__ t2w,
                             const float* __restrict__ noise) {
    int t = blockIdx.x * blockDim.x + threadIdx.x;
    if (t >= N_NODES * H2) return;
    int node = t >> 4, j = t & 15;
    float mean = dnorm(node) * g_agg2[t];
    float sum = 0.f;
    #pragma unroll
    for (int c = 0; c < H1; c++)
        sum += (g_zauto[node * H1 + c] + ALPHA * g_h[node * H1 + c]) * __ldg(&t2w[c * H2 + j]);
    g_z[t] = noise[t] * expf(sum) + mean;
}

// ---------------- out = sigmoid(z @ z^T), 128x128 tiles, 8x8/thread, f32x2 ---
__global__ __launch_bounds__(256) void zzt_kernel(float* __restrict__ out) {
    __shared__ float zr[H2][132];   // [k][row]
    __shared__ float zc[H2][132];   // [k][col]

    const int tid = threadIdx.x;
    const int rb = blockIdx.y * 128, cb = blockIdx.x * 128;

    #pragma unroll
    for (int i = 0; i < 2; i++) {
        int sIdx = tid + i * 256;
        int row = sIdx >> 2, kq = sIdx & 3;
        float4 v = *(const float4*)&g_z[(size_t)(rb + row) * H2 + kq * 4];
        zr[kq * 4 + 0][row] = v.x; zr[kq * 4 + 1][row] = v.y;
        zr[kq * 4 + 2][row] = v.z; zr[kq * 4 + 3][row] = v.w;
        float4 w = *(const float4*)&g_z[(size_t)(cb + row) * H2 + kq * 4];
        zc[kq * 4 + 0][row] = w.x; zc[kq * 4 + 1][row] = w.y;
        zc[kq * 4 + 2][row] = w.z; zc[kq * 4 + 3][row] = w.w;
    }
    __syncthreads();

    const int tc = tid & 15, tr = tid >> 4;
    const int r4 = tr * 4, c4 = tc * 4;

    ull acc[8][4] = {};
    #pragma unroll
    for (int k = 0; k < H2; k++) {
        float4 a0 = *(const float4*)&zr[k][r4];
        float4 a1 = *(const float4*)&zr[k][r4 + 64];
        ulonglong2 b01 = *(ulonglong2*)&zc[k][c4];
        ulonglong2 b23 = *(ulonglong2*)&zc[k][c4 + 64];
        ull a[8] = { dup2(a0.x), dup2(a0.y), dup2(a0.z), dup2(a0.w),
                     dup2(a1.x), dup2(a1.y), dup2(a1.z), dup2(a1.w) };
        ull b[4] = { b01.x, b01.y, b23.x, b23.y };
        #pragma unroll
        for (int i = 0; i < 8; i++) {
            ffma2(acc[i][0], a[i], b[0]);
            ffma2(acc[i][1], a[i], b[1]);
            ffma2(acc[i][2], a[i], b[2]);
            ffma2(acc[i][3], a[i], b[3]);
        }
    }

    #pragma unroll
    for (int i = 0; i < 8; i++) {
        int row = rb + r4 + (i < 4 ? i : 60 + i);
        float2 p0 = unpk(acc[i][0]), p1 = unpk(acc[i][1]);
        float2 p2 = unpk(acc[i][2]), p3 = unpk(acc[i][3]);
        float4 o0, o1;
        o0.x = sigm(p0.x); o0.y = sigm(p0.y); o0.z = sigm(p1.x); o0.w = sigm(p1.y);
        o1.x = sigm(p2.x); o1.y = sigm(p2.y); o1.z = sigm(p3.x); o1.w = sigm(p3.y);
        stcs4(&out[(size_t)row * N_NODES + cb + c4],      o0);
        stcs4(&out[(size_t)row * N_NODES + cb + c4 + 64], o1);
    }
}

// ---------------- launcher ----------------
extern "C" void kernel_launch(void* const* d_in, const int* in_sizes, int n_in,
                              void* d_out, int out_size) {
    const float* feat   = (const float*)d_in[0];
    const float* W0     = (const float*)d_in[1];
    const float* Wm     = (const float*)d_in[2];
    const float* gate_w = (const float*)d_in[3];
    const float* gate_b = (const float*)d_in[4];
    const float* t2w    = (const float*)d_in[5];
    const float* noise  = (const float*)d_in[6];
    const int*   src    = (const int*)d_in[7];
    const int*   dst    = (const int*)d_in[8];
    float* out = (float*)d_out;

    init_kernel<<<(N_NODES * H1) / 256, 256>>>(W0);
    gemm1_kernel<<<dim3(N_NODES / 128, 16), 256>>>(feat, dst);
    edge_h_kernel<<<(E_EDGES * 8) / 256, 256>>>(src, dst);
    relu_hw_kernel<<<N_NODES / 8, 256>>>(Wm);
    edge2_kernel<<<(E_EDGES * 8) / 256, 256>>>(src, dst, gate_w, gate_b);
    nodez_kernel<<<(N_NODES * H2) / 256, 256>>>(t2w, noise);
    zzt_kernel<<<dim3(64, 64), 256>>>(out);
}